// round 1
// baseline (speedup 1.0000x reference)
#include <cuda_runtime.h>

#define NN 100000
#define NE 1000000
#define DD 64
#define NRELTAB 401
#define BB 8

// Scratch (static device globals — no runtime allocation)
__device__ float g_hsproj[NN * DD];   // hidden @ Ws^T
__device__ float g_tr[NRELTAB * DD];  // rel_emb @ Wr^T
__device__ float g_tqr[BB * DD];      // rel_emb[q_rel] @ Wqr^T + b
__device__ float g_agg[NN * DD];      // segment-sum accumulator

// ---------------------------------------------------------------------------
// Zero the aggregation buffer (grid-stride float4 stores)
// ---------------------------------------------------------------------------
__global__ void zero_agg_kernel() {
    int i = blockIdx.x * blockDim.x + threadIdx.x;
    int stride = gridDim.x * blockDim.x;
    float4* p = (float4*)g_agg;
    const int n4 = NN * DD / 4;
    for (int j = i; j < n4; j += stride) p[j] = make_float4(0.f, 0.f, 0.f, 0.f);
}

// ---------------------------------------------------------------------------
// Row GEMM: out[m][a] = sum_k in[m][k] * W[a][k]   (M x 64 x 64)
// One thread per output row. W staged in smem; (a,kc) loop indices are
// warp-uniform -> all smem reads are broadcasts (conflict-free).
// ---------------------------------------------------------------------------
__device__ __forceinline__ void rowgemm_body(const float* __restrict__ in,
                                             const float* __restrict__ Wg,
                                             float* __restrict__ out, int M) {
    __shared__ float Wsm[DD * DD];
    for (int i = threadIdx.x; i < DD * DD / 4; i += blockDim.x)
        ((float4*)Wsm)[i] = ((const float4*)Wg)[i];
    __syncthreads();

    int row = blockIdx.x * blockDim.x + threadIdx.x;
    if (row >= M) return;

    float acc[DD];
#pragma unroll
    for (int a = 0; a < DD; a++) acc[a] = 0.f;

    const float4* inr = (const float4*)(in + (size_t)row * DD);
#pragma unroll 4
    for (int kc = 0; kc < DD / 4; kc++) {
        float4 h = inr[kc];
#pragma unroll
        for (int a = 0; a < DD; a++) {
            float4 w = ((const float4*)(Wsm + a * DD))[kc];
            acc[a] = fmaf(h.x, w.x, fmaf(h.y, w.y, fmaf(h.z, w.z, fmaf(h.w, w.w, acc[a]))));
        }
    }

    float4* o = (float4*)(out + (size_t)row * DD);
#pragma unroll
    for (int a = 0; a < DD / 4; a++)
        o[a] = make_float4(acc[4 * a], acc[4 * a + 1], acc[4 * a + 2], acc[4 * a + 3]);
}

__global__ void gemm_hsproj_kernel(const float* __restrict__ hidden,
                                   const float* __restrict__ Ws) {
    rowgemm_body(hidden, Ws, g_hsproj, NN);
}

__global__ void gemm_out_kernel(const float* __restrict__ Wh,
                                float* __restrict__ out) {
    rowgemm_body(g_agg, Wh, out, NN);
}

// ---------------------------------------------------------------------------
// Small relation projections: out[r][a] = sum_k emb[src(r)][k]*W[a][k] (+bias)
// One block (64 threads) per relation row. W in smem padded to kill the
// 32-way bank conflict of the a-strided access.
// ---------------------------------------------------------------------------
__device__ __forceinline__ void relproj_body(const float* __restrict__ emb,
                                             const float* __restrict__ W,
                                             const float* __restrict__ bias,
                                             const int* __restrict__ qrel,
                                             float* __restrict__ out) {
    __shared__ float Wsm[DD * 65];
    __shared__ float row[DD];
    int a = threadIdx.x;  // 0..63
    for (int i = a; i < DD * DD; i += DD)
        Wsm[(i >> 6) * 65 + (i & 63)] = W[i];
    int r = blockIdx.x;
    int src = qrel ? qrel[r] : r;
    row[a] = emb[src * DD + a];
    __syncthreads();

    float acc = bias ? bias[a] : 0.f;
#pragma unroll
    for (int k = 0; k < DD; k++) acc = fmaf(row[k], Wsm[a * 65 + k], acc);
    out[r * DD + a] = acc;
}

__global__ void proj_tr_kernel(const float* __restrict__ emb,
                               const float* __restrict__ Wr) {
    relproj_body(emb, Wr, nullptr, nullptr, g_tr);
}

__global__ void proj_tqr_kernel(const float* __restrict__ emb,
                                const float* __restrict__ Wqr,
                                const float* __restrict__ bias,
                                const int* __restrict__ qrel) {
    relproj_body(emb, Wqr, bias, qrel, g_tqr);
}

// ---------------------------------------------------------------------------
// Edge kernel: one warp per edge, float2 per lane (D=64).
//   pre = Hs_proj[sub] + Tr[rel] + Tqr[r_idx]         (bias already in Tqr)
//   alpha = sigmoid( dot(relu(pre), walpha_w) + walpha_b )
//   atomically add alpha * (hidden[sub] + rel_emb[rel]) into g_agg[obj]
// ---------------------------------------------------------------------------
__global__ void edge_kernel(const int* __restrict__ edges,
                            const float* __restrict__ hidden,
                            const float* __restrict__ rel_emb,
                            const float* __restrict__ walpha_w,
                            const float* __restrict__ walpha_b) {
    unsigned gtid = blockIdx.x * blockDim.x + threadIdx.x;
    int gw = (int)(gtid >> 5);
    if (gw >= NE) return;
    int lane = threadIdx.x & 31;

    const int* e = edges + (size_t)gw * 6;
    int r_idx = __ldg(e + 0);
    int rel   = __ldg(e + 2);
    int sub   = __ldg(e + 4);
    int obj   = __ldg(e + 5);

    int c = lane * 2;
    float2 hsp = *(const float2*)(g_hsproj + (size_t)sub * DD + c);
    float2 tr  = *(const float2*)(g_tr + rel * DD + c);
    float2 tqr = *(const float2*)(g_tqr + r_idx * DD + c);
    float2 wv  = __ldg((const float2*)walpha_w + lane);

    float px = hsp.x + tr.x + tqr.x;
    float py = hsp.y + tr.y + tqr.y;
    float part = fmaxf(px, 0.f) * wv.x + fmaxf(py, 0.f) * wv.y;
#pragma unroll
    for (int o = 16; o > 0; o >>= 1)
        part += __shfl_xor_sync(0xffffffffu, part, o);

    float z = part + __ldg(walpha_b);
    float alpha = 1.f / (1.f + __expf(-z));

    float2 hs = *(const float2*)(hidden + (size_t)sub * DD + c);
    float2 hr = *(const float2*)(rel_emb + rel * DD + c);

    float* dst = g_agg + (size_t)obj * DD + c;
    atomicAdd(dst,     alpha * (hs.x + hr.x));
    atomicAdd(dst + 1, alpha * (hs.y + hr.y));
}

// ---------------------------------------------------------------------------
// Inputs (metadata order):
//  0 q_sub[8] i32, 1 q_rel[8] i32, 2 hidden[100000,64] f32, 3 edges[1000000,6] i32,
//  4 nodes[100000,2] i32, 5 old_nodes_new_idx[50000] i32, 6 batchsize i32,
//  7 rel_emb[401,64] f32, 8 Ws[64,64], 9 Wr[64,64], 10 Wqr_w[64,64], 11 Wqr_b[64],
// 12 walpha_w[1,64], 13 walpha_b[1], 14 Wh[64,64]
// Output: hidden_new[100000,64] f32
// ---------------------------------------------------------------------------
extern "C" void kernel_launch(void* const* d_in, const int* in_sizes, int n_in,
                              void* d_out, int out_size) {
    const int*   q_rel    = (const int*)d_in[1];
    const float* hidden   = (const float*)d_in[2];
    const int*   edges    = (const int*)d_in[3];
    const float* rel_emb  = (const float*)d_in[7];
    const float* Ws       = (const float*)d_in[8];
    const float* Wr       = (const float*)d_in[9];
    const float* Wqr_w    = (const float*)d_in[10];
    const float* Wqr_b    = (const float*)d_in[11];
    const float* walpha_w = (const float*)d_in[12];
    const float* walpha_b = (const float*)d_in[13];
    const float* Wh       = (const float*)d_in[14];
    float* out = (float*)d_out;

    zero_agg_kernel<<<2048, 256>>>();
    gemm_hsproj_kernel<<<(NN + 255) / 256, 256>>>(hidden, Ws);
    proj_tr_kernel<<<NRELTAB, 64>>>(rel_emb, Wr);
    proj_tqr_kernel<<<BB, 64>>>(rel_emb, Wqr_w, Wqr_b, q_rel);
    // 8 warps per block * 125000 blocks = exactly 1M warps (one per edge)
    edge_kernel<<<NE / 8, 256>>>(edges, hidden, rel_emb, walpha_w, walpha_b);
    gemm_out_kernel<<<(NN + 255) / 256, 256>>>(Wh, out);
}

// round 2
// speedup vs baseline: 1.4022x; 1.4022x over previous
#include <cuda_runtime.h>

#define NN 100000
#define NE 1000000
#define DD 64
#define NRELTAB 401
#define BB 8

// Scratch (static device globals — no runtime allocation). 16B+ aligned for
// float4 / red.v4 access.
__device__ __align__(256) float g_hsproj[NN * DD];   // hidden @ Ws^T
__device__ __align__(256) float g_tr[NRELTAB * DD];  // rel_emb @ Wr^T
__device__ __align__(256) float g_tqr[BB * DD];      // rel_emb[q_rel] @ Wqr^T + b
__device__ __align__(256) float g_agg[NN * DD];      // segment-sum accumulator

// ---------------------------------------------------------------------------
// Row GEMM: out[m][a] = sum_k in[m][k] * W[a][k]   (M x 64 x 64)
// One thread per output row. W staged in smem; (a,kc) loop indices are
// warp-uniform -> all smem reads are broadcasts (conflict-free).
// ---------------------------------------------------------------------------
__device__ __forceinline__ void rowgemm_body(const float* __restrict__ in,
                                             const float* __restrict__ Wg,
                                             float* __restrict__ out, int M) {
    __shared__ float Wsm[DD * DD];
    for (int i = threadIdx.x; i < DD * DD / 4; i += blockDim.x)
        ((float4*)Wsm)[i] = ((const float4*)Wg)[i];
    __syncthreads();

    int row = blockIdx.x * blockDim.x + threadIdx.x;
    if (row >= M) return;

    float acc[DD];
#pragma unroll
    for (int a = 0; a < DD; a++) acc[a] = 0.f;

    const float4* inr = (const float4*)(in + (size_t)row * DD);
#pragma unroll 4
    for (int kc = 0; kc < DD / 4; kc++) {
        float4 h = inr[kc];
#pragma unroll
        for (int a = 0; a < DD; a++) {
            float4 w = ((const float4*)(Wsm + a * DD))[kc];
            acc[a] = fmaf(h.x, w.x, fmaf(h.y, w.y, fmaf(h.z, w.z, fmaf(h.w, w.w, acc[a]))));
        }
    }

    float4* o = (float4*)(out + (size_t)row * DD);
#pragma unroll
    for (int a = 0; a < DD / 4; a++)
        o[a] = make_float4(acc[4 * a], acc[4 * a + 1], acc[4 * a + 2], acc[4 * a + 3]);
}

// hsproj GEMM + fused grid-stride zeroing of g_agg (saves one launch; the
// kernel boundary before edge_kernel guarantees the zero is visible).
__global__ void gemm_hsproj_kernel(const float* __restrict__ hidden,
                                   const float* __restrict__ Ws) {
    {
        int i = blockIdx.x * blockDim.x + threadIdx.x;
        int stride = gridDim.x * blockDim.x;
        float4* p = (float4*)g_agg;
        const int n4 = NN * DD / 4;
        for (int j = i; j < n4; j += stride)
            p[j] = make_float4(0.f, 0.f, 0.f, 0.f);
    }
    rowgemm_body(hidden, Ws, g_hsproj, NN);
}

__global__ void gemm_out_kernel(const float* __restrict__ Wh,
                                float* __restrict__ out) {
    rowgemm_body(g_agg, Wh, out, NN);
}

// ---------------------------------------------------------------------------
// Fused relation projections (one launch):
//   blocks [0, NRELTAB)          : g_tr[r]  = rel_emb[r]        @ Wr^T
//   blocks [NRELTAB, NRELTAB+BB) : g_tqr[b] = rel_emb[q_rel[b]] @ Wqr^T + bias
// One 64-thread block per output row; W in padded smem (no bank conflicts).
// ---------------------------------------------------------------------------
__global__ void proj_rel_kernel(const float* __restrict__ emb,
                                const float* __restrict__ Wr,
                                const float* __restrict__ Wqr,
                                const float* __restrict__ bias,
                                const int* __restrict__ qrel) {
    __shared__ float Wsm[DD * 65];
    __shared__ float row[DD];
    int a = threadIdx.x;  // 0..63
    bool is_qr = (blockIdx.x >= NRELTAB);
    const float* W = is_qr ? Wqr : Wr;
    for (int i = a; i < DD * DD; i += DD)
        Wsm[(i >> 6) * 65 + (i & 63)] = W[i];
    int r = is_qr ? (blockIdx.x - NRELTAB) : blockIdx.x;
    int src = is_qr ? qrel[r] : r;
    row[a] = emb[src * DD + a];
    __syncthreads();

    float acc = is_qr ? bias[a] : 0.f;
#pragma unroll
    for (int k = 0; k < DD; k++) acc = fmaf(row[k], Wsm[a * 65 + k], acc);
    float* out = is_qr ? g_tqr : g_tr;
    out[r * DD + a] = acc;
}

// ---------------------------------------------------------------------------
// Edge kernel: 16 lanes per edge, float4 per lane (D=64 -> LDG.128 gathers).
//   pre   = Hs_proj[sub] + Tr[rel] + Tqr[r_idx]          (bias folded into Tqr)
//   alpha = sigmoid( dot(relu(pre), walpha_w) + walpha_b )
//   red.global.add.v4.f32 of alpha * (hidden[sub] + rel_emb[rel]) into g_agg[obj]
// 16 REDs/edge instead of 64, 128-bit gathers instead of 64-bit.
// ---------------------------------------------------------------------------
__global__ void edge_kernel(const int* __restrict__ edges,
                            const float* __restrict__ hidden,
                            const float* __restrict__ rel_emb,
                            const float* __restrict__ walpha_w,
                            const float* __restrict__ walpha_b) {
    unsigned gtid = blockIdx.x * blockDim.x + threadIdx.x;
    unsigned eid = gtid >> 4;  // 16 threads per edge
    if (eid >= NE) return;
    int l = gtid & 15;

    const int* e = edges + (size_t)eid * 6;
    int r_idx = __ldg(e + 0);
    int rel   = __ldg(e + 2);
    int sub   = __ldg(e + 4);
    int obj   = __ldg(e + 5);

    int c = l * 4;
    float4 hsp = *(const float4*)(g_hsproj + (size_t)sub * DD + c);
    float4 tr  = *(const float4*)(g_tr + rel * DD + c);
    float4 tqr = *(const float4*)(g_tqr + r_idx * DD + c);
    float4 wv  = __ldg((const float4*)walpha_w + l);

    float p0 = fmaxf(hsp.x + tr.x + tqr.x, 0.f);
    float p1 = fmaxf(hsp.y + tr.y + tqr.y, 0.f);
    float p2 = fmaxf(hsp.z + tr.z + tqr.z, 0.f);
    float p3 = fmaxf(hsp.w + tr.w + tqr.w, 0.f);
    float part = fmaf(p0, wv.x, fmaf(p1, wv.y, fmaf(p2, wv.z, p3 * wv.w)));
    // reduce across the 16-lane group (xor offsets < 16 stay in-group)
#pragma unroll
    for (int o = 8; o > 0; o >>= 1)
        part += __shfl_xor_sync(0xffffffffu, part, o);

    float z = part + __ldg(walpha_b);
    float alpha = 1.f / (1.f + __expf(-z));

    float4 hs = *(const float4*)(hidden + (size_t)sub * DD + c);
    float4 hr = *(const float4*)(rel_emb + rel * DD + c);

    float m0 = alpha * (hs.x + hr.x);
    float m1 = alpha * (hs.y + hr.y);
    float m2 = alpha * (hs.z + hr.z);
    float m3 = alpha * (hs.w + hr.w);

    float* dst = g_agg + (size_t)obj * DD + c;
    asm volatile("red.global.add.v4.f32 [%0], {%1, %2, %3, %4};"
                 :: "l"(dst), "f"(m0), "f"(m1), "f"(m2), "f"(m3)
                 : "memory");
}

// ---------------------------------------------------------------------------
// Inputs (metadata order):
//  0 q_sub[8] i32, 1 q_rel[8] i32, 2 hidden[100000,64] f32, 3 edges[1000000,6] i32,
//  4 nodes[100000,2] i32, 5 old_nodes_new_idx[50000] i32, 6 batchsize i32,
//  7 rel_emb[401,64] f32, 8 Ws[64,64], 9 Wr[64,64], 10 Wqr_w[64,64], 11 Wqr_b[64],
// 12 walpha_w[1,64], 13 walpha_b[1], 14 Wh[64,64]
// Output: hidden_new[100000,64] f32
// ---------------------------------------------------------------------------
extern "C" void kernel_launch(void* const* d_in, const int* in_sizes, int n_in,
                              void* d_out, int out_size) {
    const int*   q_rel    = (const int*)d_in[1];
    const float* hidden   = (const float*)d_in[2];
    const int*   edges    = (const int*)d_in[3];
    const float* rel_emb  = (const float*)d_in[7];
    const float* Ws       = (const float*)d_in[8];
    const float* Wr       = (const float*)d_in[9];
    const float* Wqr_w    = (const float*)d_in[10];
    const float* Wqr_b    = (const float*)d_in[11];
    const float* walpha_w = (const float*)d_in[12];
    const float* walpha_b = (const float*)d_in[13];
    const float* Wh       = (const float*)d_in[14];
    float* out = (float*)d_out;

    gemm_hsproj_kernel<<<(NN + 255) / 256, 256>>>(hidden, Ws);
    proj_rel_kernel<<<NRELTAB + BB, 64>>>(rel_emb, Wr, Wqr_w, Wqr_b, q_rel);
    // 256 threads = 16 edges/block; exact: 62500 * 16 = 1M edges
    edge_kernel<<<NE / 16, 256>>>(edges, hidden, rel_emb, walpha_w, walpha_b);
    gemm_out_kernel<<<(NN + 255) / 256, 256>>>(Wh, out);
}

// round 3
// speedup vs baseline: 1.6871x; 1.2032x over previous
#include <cuda_runtime.h>

#define NN 100000
#define NE 1000000
#define DD 64
#define NRELTAB 401
#define BB 8

#define BM 128          // GEMM block tile rows
#define TM 8            // rows per thread
#define GEMM_THREADS 256
#define NGEMM_BLOCKS ((NN + BM - 1) / BM)       // 782
#define NPROJ_ROWS (NRELTAB + BB)               // 409
#define NPROJ_BLOCKS ((NPROJ_ROWS + 3) / 4)     // 103

// Scratch (static device globals — no runtime allocation).
__device__ __align__(256) float g_hsproj[NN * DD];   // hidden @ Ws^T
__device__ __align__(256) float g_tr[NRELTAB * DD];  // rel_emb @ Wr^T
__device__ __align__(256) float g_tqr[BB * DD];      // rel_emb[q_rel] @ Wqr^T + b
__device__ __align__(256) float g_agg[NN * DD];      // segment-sum accumulator

// ---------------------------------------------------------------------------
// Register-tiled SGEMM block: out[m][a] = sum_k in[m][k] * W[a][k]
// Block computes BM=128 rows x 64 cols with 256 threads (8 rows x 4 cols each).
// smem: A tile row-major [128][64] (32KB) + W transposed Wt[k][a] (16KB) = 48KB.
// Inner loop per k: 1 LDS.128 (Wt, 2-way) + 8 broadcast LDS.32 (A) + 32 FFMA
// -> FFMA-bound (~2 warp-FFMA/cyc/SM peak).
// ---------------------------------------------------------------------------
__device__ __forceinline__ void sgemm_block(float* sm,
                                            const float* __restrict__ in,
                                            const float* __restrict__ Wg,
                                            float* __restrict__ out,
                                            int M, int blockRow) {
    float* Asm = sm;            // [128][64]
    float* Wt  = sm + BM * DD;  // [64][64]  Wt[k][a]
    int t = threadIdx.x;

    // Load W transposed (Wg is [a][k] row-major)
    for (int i = t; i < DD * DD / 4; i += GEMM_THREADS) {
        float4 w = ((const float4*)Wg)[i];
        int a = i >> 4, k = (i & 15) * 4;
        Wt[(k + 0) * DD + a] = w.x;
        Wt[(k + 1) * DD + a] = w.y;
        Wt[(k + 2) * DD + a] = w.z;
        Wt[(k + 3) * DD + a] = w.w;
    }
    // Load A tile (coalesced float4, zero-fill past M)
    int row0 = blockRow * BM;
    for (int i = t; i < BM * DD / 4; i += GEMM_THREADS) {
        int m = i >> 4;
        float4 v = make_float4(0.f, 0.f, 0.f, 0.f);
        if (row0 + m < M)
            v = ((const float4*)(in + (size_t)(row0 + m) * DD))[i & 15];
        ((float4*)Asm)[i] = v;
    }
    __syncthreads();

    int rt = t >> 4, ct = t & 15;  // 16 row-groups x 16 col-groups
    const float* arow = Asm + rt * TM * DD;
    const float4* wt4 = (const float4*)Wt + ct;

    float4 acc[TM];
#pragma unroll
    for (int r = 0; r < TM; r++) acc[r] = make_float4(0.f, 0.f, 0.f, 0.f);

#pragma unroll 8
    for (int k = 0; k < DD; k++) {
        float4 w = wt4[k * 16];
#pragma unroll
        for (int r = 0; r < TM; r++) {
            float a = arow[r * DD + k];
            acc[r].x = fmaf(a, w.x, acc[r].x);
            acc[r].y = fmaf(a, w.y, acc[r].y);
            acc[r].z = fmaf(a, w.z, acc[r].z);
            acc[r].w = fmaf(a, w.w, acc[r].w);
        }
    }

#pragma unroll
    for (int r = 0; r < TM; r++) {
        int m = row0 + rt * TM + r;
        if (m < M) ((float4*)(out + (size_t)m * DD))[ct] = acc[r];
    }
}

// ---------------------------------------------------------------------------
// Fused front kernel:
//   blocks [0, NGEMM_BLOCKS)  : zero g_agg slice + hsproj SGEMM tile
//   blocks [NGEMM_BLOCKS, +NPROJ_BLOCKS): relation projections (4 rows/block)
// ---------------------------------------------------------------------------
__global__ __launch_bounds__(GEMM_THREADS)
void fused_pre_kernel(const float* __restrict__ hidden,
                      const float* __restrict__ Ws,
                      const float* __restrict__ emb,
                      const float* __restrict__ Wr,
                      const float* __restrict__ Wqr,
                      const float* __restrict__ bias,
                      const int* __restrict__ qrel) {
    __shared__ float sm[BM * DD + DD * DD];  // 48KB, reused by both paths
    int t = threadIdx.x;

    if (blockIdx.x < NGEMM_BLOCKS) {
        // grid-stride zero of g_agg over the GEMM blocks
        {
            int i = blockIdx.x * GEMM_THREADS + t;
            int stride = NGEMM_BLOCKS * GEMM_THREADS;
            float4* p = (float4*)g_agg;
            const int n4 = NN * DD / 4;
            for (int j = i; j < n4; j += stride)
                p[j] = make_float4(0.f, 0.f, 0.f, 0.f);
        }
        sgemm_block(sm, hidden, Ws, g_hsproj, NN, blockIdx.x);
        return;
    }

    // ---- relation projection path: 4 rows per block, 64 threads per row ----
    float* WrS  = sm;               // [64][65] padded
    float* WqrS = sm + DD * 65;     // [64][65] padded
    float* rows = sm + 2 * DD * 65; // [4][64]
    for (int i = t; i < DD * DD; i += GEMM_THREADS) {
        WrS [(i >> 6) * 65 + (i & 63)] = Wr[i];
        WqrS[(i >> 6) * 65 + (i & 63)] = Wqr[i];
    }
    int sub = t >> 6, a = t & 63;
    int rid = (blockIdx.x - NGEMM_BLOCKS) * 4 + sub;
    bool valid = rid < NPROJ_ROWS;
    bool is_qr = rid >= NRELTAB;
    int r = is_qr ? (rid - NRELTAB) : rid;
    int src = valid ? (is_qr ? qrel[r] : r) : 0;
    rows[sub * DD + a] = emb[src * DD + a];
    __syncthreads();
    if (!valid) return;

    const float* W = is_qr ? WqrS : WrS;
    const float* rw = rows + sub * DD;
    float acc = is_qr ? bias[a] : 0.f;
#pragma unroll
    for (int k = 0; k < DD; k++) acc = fmaf(rw[k], W[a * 65 + k], acc);
    (is_qr ? g_tqr : g_tr)[r * DD + a] = acc;
}

__global__ __launch_bounds__(GEMM_THREADS)
void gemm_out_kernel(const float* __restrict__ Wh, float* __restrict__ out) {
    __shared__ float sm[BM * DD + DD * DD];
    sgemm_block(sm, g_agg, Wh, out, NN, blockIdx.x);
}

// ---------------------------------------------------------------------------
// Edge kernel: 16 lanes per edge, float4 per lane (LDG.128 gathers).
//   pre   = Hs_proj[sub] + Tr[rel] + Tqr[r_idx]          (bias folded into Tqr)
//   alpha = sigmoid( dot(relu(pre), walpha_w) + walpha_b )
//   red.global.add.v4.f32 of alpha * (hidden[sub] + rel_emb[rel]) into g_agg[obj]
// ---------------------------------------------------------------------------
__global__ void edge_kernel(const int* __restrict__ edges,
                            const float* __restrict__ hidden,
                            const float* __restrict__ rel_emb,
                            const float* __restrict__ walpha_w,
                            const float* __restrict__ walpha_b) {
    unsigned gtid = blockIdx.x * blockDim.x + threadIdx.x;
    unsigned eid = gtid >> 4;  // 16 threads per edge
    if (eid >= NE) return;
    int l = gtid & 15;

    const int* e = edges + (size_t)eid * 6;
    int r_idx = __ldg(e + 0);
    int rel   = __ldg(e + 2);
    int sub   = __ldg(e + 4);
    int obj   = __ldg(e + 5);

    int c = l * 4;
    float4 hsp = __ldg((const float4*)(g_hsproj + (size_t)sub * DD + c));
    float4 tr  = __ldg((const float4*)(g_tr + rel * DD + c));
    float4 tqr = __ldg((const float4*)(g_tqr + r_idx * DD + c));
    float4 wv  = __ldg((const float4*)walpha_w + l);

    float p0 = fmaxf(hsp.x + tr.x + tqr.x, 0.f);
    float p1 = fmaxf(hsp.y + tr.y + tqr.y, 0.f);
    float p2 = fmaxf(hsp.z + tr.z + tqr.z, 0.f);
    float p3 = fmaxf(hsp.w + tr.w + tqr.w, 0.f);
    float part = fmaf(p0, wv.x, fmaf(p1, wv.y, fmaf(p2, wv.z, p3 * wv.w)));
#pragma unroll
    for (int o = 8; o > 0; o >>= 1)
        part += __shfl_xor_sync(0xffffffffu, part, o);

    float z = part + __ldg(walpha_b);
    float alpha = 1.f / (1.f + __expf(-z));

    float4 hs = __ldg((const float4*)(hidden + (size_t)sub * DD + c));
    float4 hr = __ldg((const float4*)(rel_emb + rel * DD + c));

    float m0 = alpha * (hs.x + hr.x);
    float m1 = alpha * (hs.y + hr.y);
    float m2 = alpha * (hs.z + hr.z);
    float m3 = alpha * (hs.w + hr.w);

    float* dst = g_agg + (size_t)obj * DD + c;
    asm volatile("red.global.add.v4.f32 [%0], {%1, %2, %3, %4};"
                 :: "l"(dst), "f"(m0), "f"(m1), "f"(m2), "f"(m3)
                 : "memory");
}

// ---------------------------------------------------------------------------
// Inputs (metadata order):
//  0 q_sub[8] i32, 1 q_rel[8] i32, 2 hidden[100000,64] f32, 3 edges[1000000,6] i32,
//  4 nodes[100000,2] i32, 5 old_nodes_new_idx[50000] i32, 6 batchsize i32,
//  7 rel_emb[401,64] f32, 8 Ws[64,64], 9 Wr[64,64], 10 Wqr_w[64,64], 11 Wqr_b[64],
// 12 walpha_w[1,64], 13 walpha_b[1], 14 Wh[64,64]
// Output: hidden_new[100000,64] f32
// ---------------------------------------------------------------------------
extern "C" void kernel_launch(void* const* d_in, const int* in_sizes, int n_in,
                              void* d_out, int out_size) {
    const int*   q_rel    = (const int*)d_in[1];
    const float* hidden   = (const float*)d_in[2];
    const int*   edges    = (const int*)d_in[3];
    const float* rel_emb  = (const float*)d_in[7];
    const float* Ws       = (const float*)d_in[8];
    const float* Wr       = (const float*)d_in[9];
    const float* Wqr_w    = (const float*)d_in[10];
    const float* Wqr_b    = (const float*)d_in[11];
    const float* walpha_w = (const float*)d_in[12];
    const float* walpha_b = (const float*)d_in[13];
    const float* Wh       = (const float*)d_in[14];
    float* out = (float*)d_out;

    fused_pre_kernel<<<NGEMM_BLOCKS + NPROJ_BLOCKS, GEMM_THREADS>>>(
        hidden, Ws, rel_emb, Wr, Wqr_w, Wqr_b, q_rel);
    edge_kernel<<<NE / 16, 256>>>(edges, hidden, rel_emb, walpha_w, walpha_b);
    gemm_out_kernel<<<NGEMM_BLOCKS, GEMM_THREADS>>>(Wh, out);
}